// round 15
// baseline (speedup 1.0000x reference)
#include <cuda_runtime.h>
#include <cuda_fp16.h>
#include <math.h>

#define N_NODES 40962
#define N_EDGES 245760
#define KG 10
#define GMM_EPS 1e-15f
#define K1 704      // 640 (agg1) + 64 (x row -> root1)
#define K2 1408     // 640 (agg2) + 64 (h) + 640 (aggs) + 64 (x)
#define NB 161      // scan blocks: ceil(40962/256)

// packed f32x2 helpers (sm_103a: FFMA2 only reachable via PTX fma.rn.f32x2)
#define PK64(d, lo, hi) \
    asm("mov.b64 %0, {%1, %2};" : "=l"(d) : "f"(lo), "f"(hi))
#define UPK64(lo, hi, s) \
    asm("mov.b64 {%0, %1}, %2;" : "=f"(lo), "=f"(hi) : "l"(s))
#define FMA2(acc, a, b) \
    asm("fma.rn.f32x2 %0, %1, %2, %0;" : "+l"(acc) : "l"(a), "l"(b))

// ---------------- scratch (device globals; no runtime allocation) -------------
__device__ int    d_cnt[N_NODES];
__device__ int    d_cur[N_NODES];
__device__ int    d_offs[N_NODES + 1];
__device__ float  d_dinv[N_NODES];
__device__ int2   d_se[N_EDGES + 2];                 // +2 pad: unconditional prefetch
__device__ __half2 d_xh[(size_t)N_NODES * 32];       // x as half2 (channel pairs)
__device__ __half2 d_hh[(size_t)N_NODES * 32];       // h as half2
__device__ __half2 d_t1h[(size_t)N_NODES * (K1 / 2)];
__device__ __half2 d_t2h[(size_t)N_NODES * (K2 / 2)];
__device__ __half d_B1h[64 * K1];                    // [n][k] transposed
__device__ __half d_B2h[128 * K2];                   // [n][k] transposed
__device__ float  d_bias2[128];

// ---------------- prep kernels ------------------------------------------------
// histogram of dst + x->half2 conversion + d_se pad init
__global__ void hist_dst(const int* __restrict__ ei, const float* __restrict__ x) {
    int e = blockIdx.x * blockDim.x + threadIdx.x;
    if (e < N_EDGES) atomicAdd(&d_cnt[ei[N_EDGES + e]], 1);
    if (e == 0) {
        d_se[N_EDGES]     = make_int2(0, 0);
        d_se[N_EDGES + 1] = make_int2(0, 0);
    }
    const float2* x2 = (const float2*)x;
    const int total = N_NODES * 32;
    const int stride = gridDim.x * blockDim.x;
    for (int i = e; i < total; i += stride) {
        float2 v = x2[i];
        d_xh[i] = __floats2half2_rn(v.x, v.y);
    }
}

// pure scan: per-block base from global resum, then local exclusive scan
__global__ void scan_all() {
    __shared__ int sh1[8];
    __shared__ int sh2[8];
    __shared__ int bbase;
    int t = threadIdx.x, lane = t & 31, w = t >> 5;

    int lim = blockIdx.x * 256;
    int acc = 0;
    for (int j = t; j < lim; j += 256) acc += d_cnt[j];
    #pragma unroll
    for (int o = 16; o; o >>= 1) acc += __shfl_xor_sync(0xffffffffu, acc, o);
    if (lane == 0) sh1[w] = acc;
    __syncthreads();
    if (t == 0) {
        int s = 0;
        #pragma unroll
        for (int j = 0; j < 8; ++j) s += sh1[j];
        bbase = s;
    }
    __syncthreads();

    int i = lim + t;
    int v = (i < N_NODES) ? d_cnt[i] : 0;
    int s = v;
    #pragma unroll
    for (int o = 1; o < 32; o <<= 1) {
        int n = __shfl_up_sync(0xffffffffu, s, o);
        if (lane >= o) s += n;
    }
    if (lane == 31) sh2[w] = s;
    __syncthreads();
    if (w == 0 && lane < 8) {
        int xx = sh2[lane];
        #pragma unroll
        for (int o = 1; o < 8; o <<= 1) {
            int n = __shfl_up_sync(0xffu, xx, o);
            if (lane >= o) xx += n;
        }
        sh2[lane] = xx;
    }
    __syncthreads();
    int excl = s - v + (w > 0 ? sh2[w - 1] : 0);
    if (i < N_NODES) {
        d_offs[i] = bbase + excl;
        d_dinv[i] = 1.0f / (float)max(v, 1);
    }
    if (t == 0 && blockIdx.x == 0) d_offs[N_NODES] = N_EDGES;
}

// standalone weave: big B matrices (transposed [n][k], half) + combined bias
__global__ void bweave(const float* __restrict__ g1, const float* __restrict__ root1,
                       const float* __restrict__ g2, const float* __restrict__ root2,
                       const float* __restrict__ gs, const float* __restrict__ roots,
                       const float* __restrict__ b2, const float* __restrict__ bs) {
    int idx = blockIdx.x * blockDim.x + threadIdx.x;
    if (idx < 128) d_bias2[idx] = b2[idx] + bs[idx];
    if (idx < 64 * K1) {
        int n = idx / K1, k = idx % K1;
        float v;
        if (k < 640) v = g1[(k & 63) * 640 + (k >> 6) * 64 + n];
        else         v = root1[(k - 640) * 64 + n];
        d_B1h[idx] = __float2half_rn(v);
    }
    if (idx < 128 * K2) {
        int n = idx / K2, k = idx % K2;
        float v;
        if (k < 640)       v = g2[(k & 63) * 1280 + (k >> 6) * 128 + n];
        else if (k < 704)  v = root2[(k - 640) * 128 + n];
        else if (k < 1344) { int kk = k - 704; v = gs[(kk & 63) * 1280 + (kk >> 6) * 128 + n]; }
        else               v = roots[(k - 1344) * 128 + n];
        d_B2h[idx] = __float2half_rn(v);
    }
}

// dst-sort scatter: (src, edge-id); also zero d_cnt for next replay
__global__ void scatter_idx(const int* __restrict__ ei) {
    int e = blockIdx.x * blockDim.x + threadIdx.x;
    if (e < N_NODES) d_cnt[e] = 0;
    if (e >= N_EDGES) return;
    int src = ei[e];
    int dst = ei[N_EDGES + e];
    int pos = d_offs[dst] + atomicAdd(&d_cur[dst], 1);
    d_se[pos] = make_int2(src, e);
}

// ---------------- pass X: warp/node, fp16 x-gather, FFMA2 accumulators --------
// ax[k] = (a1[k].x, as[k].x) packed; ay[k] = (a1[k].y, as[k].y) packed.
__global__ __launch_bounds__(256) void tbuildX(
    const float* __restrict__ pseudo,
    const float* __restrict__ mu1, const float* __restrict__ sg1,
    const float* __restrict__ mus, const float* __restrict__ sgs)
{
    int gid = blockIdx.x * blockDim.x + threadIdx.x;
    if (gid < N_NODES) d_cur[gid] = 0;     // zero cursor for next replay
    int gw = gid >> 5;
    int lane = threadIdx.x & 31;
    if (gw >= N_NODES) return;

    // lanes 0..9: conv1 params; lanes 10..19: shortcut params
    float m0 = 0.f, m1 = 0.f, i0 = 0.f, i1 = 0.f;
    if (lane < KG) {
        m0 = mu1[2 * lane]; m1 = mu1[2 * lane + 1];
        float s0 = sg1[2 * lane], s1 = sg1[2 * lane + 1];
        i0 = -0.5f / (GMM_EPS + s0 * s0);
        i1 = -0.5f / (GMM_EPS + s1 * s1);
    } else if (lane < 2 * KG) {
        int k = lane - KG;
        m0 = mus[2 * k]; m1 = mus[2 * k + 1];
        float s0 = sgs[2 * k], s1 = sgs[2 * k + 1];
        i0 = -0.5f / (GMM_EPS + s0 * s0);
        i1 = -0.5f / (GMM_EPS + s1 * s1);
    }

    const float2* ps2 = (const float2*)pseudo;
    int beg = d_offs[gw], end = d_offs[gw + 1];
    float dinv = d_dinv[gw];
    unsigned long long ax[KG], ay[KG];
    #pragma unroll
    for (int k = 0; k < KG; ++k) { ax[k] = 0ull; ay[k] = 0ull; }

    // unconditional 2-deep pipeline (d_se padded by 2, pad src=0 is valid)
    int2 sN = d_se[beg + 1];
    {
        int2 sB = d_se[beg];
        float2 pC = ps2[sB.y];
        __half2 xC = d_xh[(size_t)sB.x * 32 + lane];
        for (int e = beg; e < end; ++e) {
            float2 pN = ps2[sN.y];
            __half2 xN = d_xh[(size_t)sN.x * 32 + lane];
            sN = d_se[e + 2];
            float wv = 0.f;
            if (lane < 2 * KG) {
                float dx = pC.x - m0, dy = pC.y - m1;
                wv = __expf(dx * dx * i0 + dy * dy * i1);
            }
            float2 xf = __half22float2(xC);
            unsigned long long xdx, xdy;
            PK64(xdx, xf.x, xf.x);
            PK64(xdy, xf.y, xf.y);
            #pragma unroll
            for (int k = 0; k < KG; ++k) {
                float w1 = __shfl_sync(0xffffffffu, wv, k);
                float ws = __shfl_sync(0xffffffffu, wv, KG + k);
                unsigned long long wp;
                PK64(wp, w1, ws);
                FMA2(ax[k], wp, xdx);
                FMA2(ay[k], wp, xdy);
            }
            pC = pN; xC = xN;
        }
    }
    __half2 own = d_xh[(size_t)gw * 32 + lane];
    __half2* tr1 = d_t1h + (size_t)gw * (K1 / 2);
    __half2* tr2 = d_t2h + (size_t)gw * (K2 / 2);
    #pragma unroll
    for (int k = 0; k < KG; ++k) {
        float a1x, asx, a1y, asy;
        UPK64(a1x, asx, ax[k]);
        UPK64(a1y, asy, ay[k]);
        tr1[k * 32 + lane]       = __floats2half2_rn(a1x * dinv, a1y * dinv);
        tr2[352 + k * 32 + lane] = __floats2half2_rn(asx * dinv, asy * dinv);
    }
    tr1[320 + lane] = own;
    tr2[672 + lane] = own;
}

// ---------------- pass H: warp/node, fp16 h-gather, FFMA2 accumulators --------
// acc[k] = (a2[k].x, a2[k].y) packed.
__global__ __launch_bounds__(256) void tbuildH(
    const float* __restrict__ pseudo,
    const float* __restrict__ mu2, const float* __restrict__ sg2)
{
    int gw = (blockIdx.x * blockDim.x + threadIdx.x) >> 5;
    int lane = threadIdx.x & 31;
    if (gw >= N_NODES) return;

    float m0 = 0.f, m1 = 0.f, i0 = 0.f, i1 = 0.f;
    if (lane < KG) {
        m0 = mu2[2 * lane]; m1 = mu2[2 * lane + 1];
        float s0 = sg2[2 * lane], s1 = sg2[2 * lane + 1];
        i0 = -0.5f / (GMM_EPS + s0 * s0);
        i1 = -0.5f / (GMM_EPS + s1 * s1);
    }

    const float2* ps2 = (const float2*)pseudo;
    int beg = d_offs[gw], end = d_offs[gw + 1];
    float dinv = d_dinv[gw];
    unsigned long long acc[KG];
    #pragma unroll
    for (int k = 0; k < KG; ++k) acc[k] = 0ull;

    int2 sN = d_se[beg + 1];
    {
        int2 sB = d_se[beg];
        float2 pC = ps2[sB.y];
        __half2 hC = d_hh[(size_t)sB.x * 32 + lane];
        for (int e = beg; e < end; ++e) {
            float2 pN = ps2[sN.y];
            __half2 hN = d_hh[(size_t)sN.x * 32 + lane];
            sN = d_se[e + 2];
            float wv = 0.f;
            if (lane < KG) {
                float dx = pC.x - m0, dy = pC.y - m1;
                wv = __expf(dx * dx * i0 + dy * dy * i1);
            }
            float2 hf = __half22float2(hC);
            unsigned long long hp;
            PK64(hp, hf.x, hf.y);
            #pragma unroll
            for (int k = 0; k < KG; ++k) {
                float w = __shfl_sync(0xffffffffu, wv, k);
                unsigned long long wd;
                PK64(wd, w, w);
                FMA2(acc[k], wd, hp);
            }
            pC = pN; hC = hN;
        }
    }
    __half2* tr = d_t2h + (size_t)gw * (K2 / 2);
    #pragma unroll
    for (int k = 0; k < KG; ++k) {
        float a2x, a2y;
        UPK64(a2x, a2y, acc[k]);
        tr[k * 32 + lane] = __floats2half2_rn(a2x * dinv, a2y * dinv);
    }
    tr[320 + lane] = d_hh[(size_t)gw * 32 + lane];
}

// ---------------- fp16 GEMM #1: BM=BN=64, m16n8k16, cp.async, half2 out -------
#define CPA16(dst, src) \
    asm volatile("cp.async.cg.shared.global [%0], [%1], 16;\n" :: "r"(dst), "l"(src))

__global__ __launch_bounds__(256) void gemm_h(
    const __half* __restrict__ A, const __half* __restrict__ Bt,
    __half2* __restrict__ Ch, int M, int N, int K, const float* __restrict__ bias)
{
    __shared__ __align__(16) __half As[2][64][72];
    __shared__ __align__(16) __half Bs[2][64][72];
    const int tid = threadIdx.x;
    const int bm = blockIdx.y * 64;
    const int bn = blockIdx.x * 64;
    const int wid = tid >> 5, l = tid & 31;
    const int wr = wid & 3, wc = wid >> 2;     // 4 m-warps x 2 n-warps
    const int tg = l >> 2, ti = l & 3;

    const int row = tid >> 2, q = tid & 3;
    const bool av = (bm + row) < M;
    const __half* apb = A + (size_t)(bm + row) * K + q * 16;
    const __half* bpb = Bt + (size_t)(bn + row) * K + q * 16;
    const unsigned sA0 = (unsigned)__cvta_generic_to_shared(&As[0][row][q * 16]);
    const unsigned sB0 = (unsigned)__cvta_generic_to_shared(&Bs[0][row][q * 16]);
    const unsigned STGA = 64 * 72 * 2;

    auto load_stage = [&](int s, int kt) {
        const __half* a = apb + kt * 64;
        const __half* b = bpb + kt * 64;
        unsigned da = sA0 + s * STGA, db = sB0 + s * STGA;
        if (av) {
            CPA16(da,      a);
            CPA16(da + 16, a + 8);
        } else {
            *(uint4*)&As[s][row][q * 16]     = make_uint4(0, 0, 0, 0);
            *(uint4*)&As[s][row][q * 16 + 8] = make_uint4(0, 0, 0, 0);
        }
        CPA16(db,      b);
        CPA16(db + 16, b + 8);
        asm volatile("cp.async.commit_group;\n");
    };

    float acc[4][4] = {};
    const int nk = K >> 6;
    load_stage(0, 0);
    for (int kt = 0; kt < nk; ++kt) {
        int cur = kt & 1;
        if (kt + 1 < nk) {
            load_stage(cur ^ 1, kt + 1);
            asm volatile("cp.async.wait_group 1;\n");
        } else {
            asm volatile("cp.async.wait_group 0;\n");
        }
        __syncthreads();
        #pragma unroll
        for (int ks = 0; ks < 4; ++ks) {
            int kb = ks * 16 + 2 * ti;
            unsigned a0 = *(const unsigned*)&As[cur][wr * 16 + tg    ][kb    ];
            unsigned a1 = *(const unsigned*)&As[cur][wr * 16 + tg + 8][kb    ];
            unsigned a2 = *(const unsigned*)&As[cur][wr * 16 + tg    ][kb + 8];
            unsigned a3 = *(const unsigned*)&As[cur][wr * 16 + tg + 8][kb + 8];
            #pragma unroll
            for (int nt = 0; nt < 4; ++nt) {
                int bc = wc * 32 + nt * 8 + tg;
                unsigned b0 = *(const unsigned*)&Bs[cur][bc][kb    ];
                unsigned b1 = *(const unsigned*)&Bs[cur][bc][kb + 8];
                asm volatile(
                    "mma.sync.aligned.m16n8k16.row.col.f32.f16.f16.f32 "
                    "{%0,%1,%2,%3}, {%4,%5,%6,%7}, {%8,%9}, {%0,%1,%2,%3};"
                    : "+f"(acc[nt][0]), "+f"(acc[nt][1]),
                      "+f"(acc[nt][2]), "+f"(acc[nt][3])
                    : "r"(a0), "r"(a1), "r"(a2), "r"(a3), "r"(b0), "r"(b1));
            }
        }
        __syncthreads();
    }
    #pragma unroll
    for (int nt = 0; nt < 4; ++nt) {
        int col = bn + wc * 32 + nt * 8 + 2 * ti;
        float bv0 = bias[col], bv1 = bias[col + 1];
        int r0 = bm + wr * 16 + tg, r1 = r0 + 8;
        float v00 = fmaxf(acc[nt][0] + bv0, 0.f), v01 = fmaxf(acc[nt][1] + bv1, 0.f);
        float v10 = fmaxf(acc[nt][2] + bv0, 0.f), v11 = fmaxf(acc[nt][3] + bv1, 0.f);
        if (r0 < M) Ch[(size_t)r0 * (N / 2) + col / 2] = __floats2half2_rn(v00, v01);
        if (r1 < M) Ch[(size_t)r1 * (N / 2) + col / 2] = __floats2half2_rn(v10, v11);
    }
}

// ---------------- fp16 GEMM #2: BM=64, BN=128, 32x32 warp tiles, fp32 out -----
__global__ __launch_bounds__(256) void gemm_h2(
    const __half* __restrict__ A, const __half* __restrict__ Bt,
    float* __restrict__ C, int M, int K, const float* __restrict__ bias)
{
    __shared__ __align__(16) __half As[2][64][72];
    __shared__ __align__(16) __half Bs[2][128][72];
    const int tid = threadIdx.x;
    const int bm = blockIdx.x * 64;
    const int wid = tid >> 5, l = tid & 31;
    const int wr = wid & 1;        // 2 m-warps: rows wr*32..+31
    const int wc = wid >> 1;       // 4 n-warps: cols wc*32..+31
    const int tg = l >> 2, ti = l & 3;

    const int arow = tid >> 2, aq = tid & 3;
    const int brow = tid >> 1, bq = tid & 1;
    const bool av = (bm + arow) < M;
    const __half* apb = A + (size_t)(bm + arow) * K + aq * 16;
    const __half* bpb = Bt + (size_t)brow * K + bq * 32;
    const unsigned sA0 = (unsigned)__cvta_generic_to_shared(&As[0][arow][aq * 16]);
    const unsigned sB0 = (unsigned)__cvta_generic_to_shared(&Bs[0][brow][bq * 32]);
    const unsigned STGA = 64 * 72 * 2;
    const unsigned STGB = 128 * 72 * 2;

    auto load_stage = [&](int s, int kt) {
        const __half* a = apb + kt * 64;
        unsigned da = sA0 + s * STGA;
        if (av) {
            CPA16(da,      a);
            CPA16(da + 16, a + 8);
        } else {
            *(uint4*)&As[s][arow][aq * 16]     = make_uint4(0, 0, 0, 0);
            *(uint4*)&As[s][arow][aq * 16 + 8] = make_uint4(0, 0, 0, 0);
        }
        const __half* b = bpb + kt * 64;
        unsigned db = sB0 + s * STGB;
        CPA16(db,      b);
        CPA16(db + 16, b + 8);
        CPA16(db + 32, b + 16);
        CPA16(db + 48, b + 24);
        asm volatile("cp.async.commit_group;\n");
    };

    float acc[2][4][4] = {};
    const int nk = K >> 6;
    load_stage(0, 0);
    for (int kt = 0; kt < nk; ++kt) {
        int cur = kt & 1;
        if (kt + 1 < nk) {
            load_stage(cur ^ 1, kt + 1);
            asm volatile("cp.async.wait_group 1;\n");
        } else {
            asm volatile("cp.async.wait_group 0;\n");
        }
        __syncthreads();
        #pragma unroll
        for (int ks = 0; ks < 4; ++ks) {
            int kb = ks * 16 + 2 * ti;
            unsigned a[2][4];
            #pragma unroll
            for (int mt = 0; mt < 2; ++mt) {
                int r0 = wr * 32 + mt * 16 + tg;
                a[mt][0] = *(const unsigned*)&As[cur][r0    ][kb    ];
                a[mt][1] = *(const unsigned*)&As[cur][r0 + 8][kb    ];
                a[mt][2] = *(const unsigned*)&As[cur][r0    ][kb + 8];
                a[mt][3] = *(const unsigned*)&As[cur][r0 + 8][kb + 8];
            }
            #pragma unroll
            for (int nt = 0; nt < 4; ++nt) {
                int bc = wc * 32 + nt * 8 + tg;
                unsigned b0 = *(const unsigned*)&Bs[cur][bc][kb    ];
                unsigned b1 = *(const unsigned*)&Bs[cur][bc][kb + 8];
                #pragma unroll
                for (int mt = 0; mt < 2; ++mt) {
                    asm volatile(
                        "mma.sync.aligned.m16n8k16.row.col.f32.f16.f16.f32 "
                        "{%0,%1,%2,%3}, {%4,%5,%6,%7}, {%8,%9}, {%0,%1,%2,%3};"
                        : "+f"(acc[mt][nt][0]), "+f"(acc[mt][nt][1]),
                          "+f"(acc[mt][nt][2]), "+f"(acc[mt][nt][3])
                        : "r"(a[mt][0]), "r"(a[mt][1]), "r"(a[mt][2]), "r"(a[mt][3]),
                          "r"(b0), "r"(b1));
                }
            }
        }
        __syncthreads();
    }
    #pragma unroll
    for (int mt = 0; mt < 2; ++mt) {
        #pragma unroll
        for (int nt = 0; nt < 4; ++nt) {
            int col = wc * 32 + nt * 8 + 2 * ti;
            float bv0 = bias[col], bv1 = bias[col + 1];
            int r0 = bm + wr * 32 + mt * 16 + tg, r1 = r0 + 8;
            if (r0 < M)
                *(float2*)(C + (size_t)r0 * 128 + col) =
                    make_float2(fmaxf(acc[mt][nt][0] + bv0, 0.f),
                                fmaxf(acc[mt][nt][1] + bv1, 0.f));
            if (r1 < M)
                *(float2*)(C + (size_t)r1 * 128 + col) =
                    make_float2(fmaxf(acc[mt][nt][2] + bv0, 0.f),
                                fmaxf(acc[mt][nt][3] + bv1, 0.f));
        }
    }
}

// ---------------- launch ------------------------------------------------------
extern "C" void kernel_launch(void* const* d_in, const int* in_sizes, int n_in,
                              void* d_out, int out_size) {
    const float* x      = (const float*)d_in[0];
    const int*   ei     = (const int*)  d_in[1];
    const float* pseudo = (const float*)d_in[2];
    const float* g1     = (const float*)d_in[3];
    const float* mu1    = (const float*)d_in[4];
    const float* sigma1 = (const float*)d_in[5];
    const float* root1  = (const float*)d_in[6];
    const float* b1     = (const float*)d_in[7];
    const float* g2     = (const float*)d_in[8];
    const float* mu2    = (const float*)d_in[9];
    const float* sigma2 = (const float*)d_in[10];
    const float* root2  = (const float*)d_in[11];
    const float* b2     = (const float*)d_in[12];
    const float* gs     = (const float*)d_in[13];
    const float* mus    = (const float*)d_in[14];
    const float* sigmas = (const float*)d_in[15];
    const float* roots  = (const float*)d_in[16];
    const float* bs     = (const float*)d_in[17];
    float* out = (float*)d_out;

    __half *t1p, *t2p, *B1p, *B2p;
    __half2 *hhp;
    float *bias2p;
    cudaGetSymbolAddress((void**)&t1p, d_t1h);
    cudaGetSymbolAddress((void**)&t2p, d_t2h);
    cudaGetSymbolAddress((void**)&hhp, d_hh);
    cudaGetSymbolAddress((void**)&B1p, d_B1h);
    cudaGetSymbolAddress((void**)&B2p, d_B2h);
    cudaGetSymbolAddress((void**)&bias2p, d_bias2);

    const int MT = (N_NODES + 63) / 64;
    const int EW = (N_EDGES + 255) / 256;
    const int NW = (N_NODES * 32 + 255) / 256;

    // prep
    hist_dst<<<EW, 256>>>(ei, x);
    scan_all<<<NB, 256>>>();
    scatter_idx<<<EW, 256>>>(ei);

    // x-pass (launch #4 -> ncu capture slot)
    tbuildX<<<NW, 256>>>(pseudo, mu1, sigma1, mus, sigmas);
    bweave<<<(128 * K2 + 255) / 256, 256>>>(g1, root1, g2, root2, gs, roots, b2, bs);
    gemm_h<<<dim3(1, MT), 256>>>(t1p, B1p, hhp, N_NODES, 64, K1, b1);

    // h-pass
    tbuildH<<<NW, 256>>>(pseudo, mu2, sigma2);
    gemm_h2<<<MT, 256>>>(t2p, B2p, out, N_NODES, K2, bias2p);
}

// round 17
// speedup vs baseline: 1.0772x; 1.0772x over previous
#include <cuda_runtime.h>
#include <cuda_fp16.h>
#include <math.h>

#define N_NODES 40962
#define N_EDGES 245760
#define KG 10
#define GMM_EPS 1e-15f
#define K1 704      // 640 (agg1) + 64 (x row -> root1)
#define K2 1408     // 640 (agg2) + 64 (h) + 640 (aggs) + 64 (x)
#define NB 161      // scan blocks: ceil(40962/256)

// ---------------- scratch (device globals; no runtime allocation) -------------
__device__ int    d_cnt[N_NODES];
__device__ int    d_cur[N_NODES];
__device__ int    d_offs[N_NODES + 1];
__device__ float  d_dinv[N_NODES];
__device__ int2   d_se[N_EDGES + 2];                 // +2 pad: unconditional prefetch
__device__ __half2 d_xh[(size_t)N_NODES * 32];       // x as half2 (channel pairs)
__device__ __half2 d_hh[(size_t)N_NODES * 32];       // h as half2
__device__ __half2 d_t1h[(size_t)N_NODES * (K1 / 2)];
__device__ __half2 d_t2h[(size_t)N_NODES * (K2 / 2)];
__device__ __half d_B1h[64 * K1];                    // [n][k] transposed
__device__ __half d_B2h[128 * K2];                   // [n][k] transposed
__device__ float  d_bias2[128];

// ---------------- prep kernels ------------------------------------------------
// histogram of dst + x->half2 conversion + d_se pad init
__global__ void hist_dst(const int* __restrict__ ei, const float* __restrict__ x) {
    int e = blockIdx.x * blockDim.x + threadIdx.x;
    if (e < N_EDGES) atomicAdd(&d_cnt[ei[N_EDGES + e]], 1);
    if (e == 0) {
        d_se[N_EDGES]     = make_int2(0, 0);
        d_se[N_EDGES + 1] = make_int2(0, 0);
    }
    const float2* x2 = (const float2*)x;
    const int total = N_NODES * 32;
    const int stride = gridDim.x * blockDim.x;
    for (int i = e; i < total; i += stride) {
        float2 v = x2[i];
        d_xh[i] = __floats2half2_rn(v.x, v.y);
    }
}

// pure scan: per-block base from global resum, then local exclusive scan
__global__ void scan_all() {
    __shared__ int sh1[8];
    __shared__ int sh2[8];
    __shared__ int bbase;
    int t = threadIdx.x, lane = t & 31, w = t >> 5;

    int lim = blockIdx.x * 256;
    int acc = 0;
    for (int j = t; j < lim; j += 256) acc += d_cnt[j];
    #pragma unroll
    for (int o = 16; o; o >>= 1) acc += __shfl_xor_sync(0xffffffffu, acc, o);
    if (lane == 0) sh1[w] = acc;
    __syncthreads();
    if (t == 0) {
        int s = 0;
        #pragma unroll
        for (int j = 0; j < 8; ++j) s += sh1[j];
        bbase = s;
    }
    __syncthreads();

    int i = lim + t;
    int v = (i < N_NODES) ? d_cnt[i] : 0;
    int s = v;
    #pragma unroll
    for (int o = 1; o < 32; o <<= 1) {
        int n = __shfl_up_sync(0xffffffffu, s, o);
        if (lane >= o) s += n;
    }
    if (lane == 31) sh2[w] = s;
    __syncthreads();
    if (w == 0 && lane < 8) {
        int xx = sh2[lane];
        #pragma unroll
        for (int o = 1; o < 8; o <<= 1) {
            int n = __shfl_up_sync(0xffu, xx, o);
            if (lane >= o) xx += n;
        }
        sh2[lane] = xx;
    }
    __syncthreads();
    int excl = s - v + (w > 0 ? sh2[w - 1] : 0);
    if (i < N_NODES) {
        d_offs[i] = bbase + excl;
        d_dinv[i] = 1.0f / (float)max(v, 1);
    }
    if (t == 0 && blockIdx.x == 0) d_offs[N_NODES] = N_EDGES;
}

// standalone weave: big B matrices (transposed [n][k], half) + combined bias
__global__ void bweave(const float* __restrict__ g1, const float* __restrict__ root1,
                       const float* __restrict__ g2, const float* __restrict__ root2,
                       const float* __restrict__ gs, const float* __restrict__ roots,
                       const float* __restrict__ b2, const float* __restrict__ bs) {
    int idx = blockIdx.x * blockDim.x + threadIdx.x;
    if (idx < 128) d_bias2[idx] = b2[idx] + bs[idx];
    if (idx < 64 * K1) {
        int n = idx / K1, k = idx % K1;
        float v;
        if (k < 640) v = g1[(k & 63) * 640 + (k >> 6) * 64 + n];
        else         v = root1[(k - 640) * 64 + n];
        d_B1h[idx] = __float2half_rn(v);
    }
    if (idx < 128 * K2) {
        int n = idx / K2, k = idx % K2;
        float v;
        if (k < 640)       v = g2[(k & 63) * 1280 + (k >> 6) * 128 + n];
        else if (k < 704)  v = root2[(k - 640) * 128 + n];
        else if (k < 1344) { int kk = k - 704; v = gs[(kk & 63) * 1280 + (kk >> 6) * 128 + n]; }
        else               v = roots[(k - 1344) * 128 + n];
        d_B2h[idx] = __float2half_rn(v);
    }
}

// dst-sort scatter: (src, edge-id); also zero d_cnt for next replay
__global__ void scatter_idx(const int* __restrict__ ei) {
    int e = blockIdx.x * blockDim.x + threadIdx.x;
    if (e < N_NODES) d_cnt[e] = 0;
    if (e >= N_EDGES) return;
    int src = ei[e];
    int dst = ei[N_EDGES + e];
    int pos = d_offs[dst] + atomicAdd(&d_cur[dst], 1);
    d_se[pos] = make_int2(src, e);
}

// ---------------- pass X: warp/node, fp16 x-gather, agg1->t1 + aggs->t2 -------
__global__ __launch_bounds__(256) void tbuildX(
    const float* __restrict__ pseudo,
    const float* __restrict__ mu1, const float* __restrict__ sg1,
    const float* __restrict__ mus, const float* __restrict__ sgs)
{
    int gid = blockIdx.x * blockDim.x + threadIdx.x;
    if (gid < N_NODES) d_cur[gid] = 0;     // zero cursor for next replay
    int gw = gid >> 5;
    int lane = threadIdx.x & 31;
    if (gw >= N_NODES) return;

    // lanes 0..9: conv1 params; lanes 10..19: shortcut params
    float m0 = 0.f, m1 = 0.f, i0 = 0.f, i1 = 0.f;
    if (lane < KG) {
        m0 = mu1[2 * lane]; m1 = mu1[2 * lane + 1];
        float s0 = sg1[2 * lane], s1 = sg1[2 * lane + 1];
        i0 = -0.5f / (GMM_EPS + s0 * s0);
        i1 = -0.5f / (GMM_EPS + s1 * s1);
    } else if (lane < 2 * KG) {
        int k = lane - KG;
        m0 = mus[2 * k]; m1 = mus[2 * k + 1];
        float s0 = sgs[2 * k], s1 = sgs[2 * k + 1];
        i0 = -0.5f / (GMM_EPS + s0 * s0);
        i1 = -0.5f / (GMM_EPS + s1 * s1);
    }

    const float2* ps2 = (const float2*)pseudo;
    int beg = d_offs[gw], end = d_offs[gw + 1];
    float dinv = d_dinv[gw];
    float2 a1[KG], as_[KG];
    #pragma unroll
    for (int k = 0; k < KG; ++k) { a1[k] = make_float2(0.f, 0.f); as_[k] = make_float2(0.f, 0.f); }

    // unconditional 2-deep pipeline (d_se padded by 2, pad src=0 is valid)
    int2 sN = d_se[beg + 1];
    {
        int2 sB = d_se[beg];
        float2 pC = ps2[sB.y];
        __half2 xC = d_xh[(size_t)sB.x * 32 + lane];
        for (int e = beg; e < end; ++e) {
            float2 pN = ps2[sN.y];
            __half2 xN = d_xh[(size_t)sN.x * 32 + lane];
            sN = d_se[e + 2];
            float wv = 0.f;
            if (lane < 2 * KG) {
                float dx = pC.x - m0, dy = pC.y - m1;
                wv = __expf(dx * dx * i0 + dy * dy * i1);
            }
            float2 xf = __half22float2(xC);
            #pragma unroll
            for (int k = 0; k < KG; ++k) {
                float w1 = __shfl_sync(0xffffffffu, wv, k);
                float ws = __shfl_sync(0xffffffffu, wv, KG + k);
                a1[k].x  = fmaf(w1, xf.x, a1[k].x);
                a1[k].y  = fmaf(w1, xf.y, a1[k].y);
                as_[k].x = fmaf(ws, xf.x, as_[k].x);
                as_[k].y = fmaf(ws, xf.y, as_[k].y);
            }
            pC = pN; xC = xN;
        }
    }
    __half2 own = d_xh[(size_t)gw * 32 + lane];
    __half2* tr1 = d_t1h + (size_t)gw * (K1 / 2);
    #pragma unroll
    for (int k = 0; k < KG; ++k)
        tr1[k * 32 + lane] = __floats2half2_rn(a1[k].x * dinv, a1[k].y * dinv);
    tr1[320 + lane] = own;

    __half2* tr2 = d_t2h + (size_t)gw * (K2 / 2);
    #pragma unroll
    for (int k = 0; k < KG; ++k)
        tr2[352 + k * 32 + lane] = __floats2half2_rn(as_[k].x * dinv, as_[k].y * dinv);
    tr2[672 + lane] = own;
}

// ---------------- pass H: warp/node, fp16 h-gather -> conv2 part of t2 --------
__global__ __launch_bounds__(256) void tbuildH(
    const float* __restrict__ pseudo,
    const float* __restrict__ mu2, const float* __restrict__ sg2)
{
    int gw = (blockIdx.x * blockDim.x + threadIdx.x) >> 5;
    int lane = threadIdx.x & 31;
    if (gw >= N_NODES) return;

    float m0 = 0.f, m1 = 0.f, i0 = 0.f, i1 = 0.f;
    if (lane < KG) {
        m0 = mu2[2 * lane]; m1 = mu2[2 * lane + 1];
        float s0 = sg2[2 * lane], s1 = sg2[2 * lane + 1];
        i0 = -0.5f / (GMM_EPS + s0 * s0);
        i1 = -0.5f / (GMM_EPS + s1 * s1);
    }

    const float2* ps2 = (const float2*)pseudo;
    int beg = d_offs[gw], end = d_offs[gw + 1];
    float dinv = d_dinv[gw];
    float2 a2[KG];
    #pragma unroll
    for (int k = 0; k < KG; ++k) a2[k] = make_float2(0.f, 0.f);

    int2 sN = d_se[beg + 1];
    {
        int2 sB = d_se[beg];
        float2 pC = ps2[sB.y];
        __half2 hC = d_hh[(size_t)sB.x * 32 + lane];
        for (int e = beg; e < end; ++e) {
            float2 pN = ps2[sN.y];
            __half2 hN = d_hh[(size_t)sN.x * 32 + lane];
            sN = d_se[e + 2];
            float wv = 0.f;
            if (lane < KG) {
                float dx = pC.x - m0, dy = pC.y - m1;
                wv = __expf(dx * dx * i0 + dy * dy * i1);
            }
            float2 hf = __half22float2(hC);
            #pragma unroll
            for (int k = 0; k < KG; ++k) {
                float w = __shfl_sync(0xffffffffu, wv, k);
                a2[k].x = fmaf(w, hf.x, a2[k].x);
                a2[k].y = fmaf(w, hf.y, a2[k].y);
            }
            pC = pN; hC = hN;
        }
    }
    __half2* tr = d_t2h + (size_t)gw * (K2 / 2);
    #pragma unroll
    for (int k = 0; k < KG; ++k)
        tr[k * 32 + lane] = __floats2half2_rn(a2[k].x * dinv, a2[k].y * dinv);
    tr[320 + lane] = d_hh[(size_t)gw * 32 + lane];
}

// ---------------- fp16 GEMM: BM=BN=64, m16n8k16, cp.async double buffer -------
// If Ch != nullptr, output relu(...) as half2 into Ch (row stride N/2 half2),
// else fp32 into C.
#define CPA16(dst, src) \
    asm volatile("cp.async.cg.shared.global [%0], [%1], 16;\n" :: "r"(dst), "l"(src))

__global__ __launch_bounds__(256) void gemm_h(
    const __half* __restrict__ A, const __half* __restrict__ Bt,
    float* __restrict__ C, __half2* __restrict__ Ch,
    int M, int N, int K, const float* __restrict__ bias)
{
    __shared__ __align__(16) __half As[2][64][72];
    __shared__ __align__(16) __half Bs[2][64][72];
    const int tid = threadIdx.x;
    const int bm = blockIdx.y * 64;
    const int bn = blockIdx.x * 64;
    const int wid = tid >> 5, l = tid & 31;
    const int wr = wid & 3, wc = wid >> 2;     // 4 m-warps x 2 n-warps
    const int tg = l >> 2, ti = l & 3;

    const int row = tid >> 2, q = tid & 3;
    const bool av = (bm + row) < M;
    const __half* apb = A + (size_t)(bm + row) * K + q * 16;
    const __half* bpb = Bt + (size_t)(bn + row) * K + q * 16;
    const unsigned sA0 = (unsigned)__cvta_generic_to_shared(&As[0][row][q * 16]);
    const unsigned sB0 = (unsigned)__cvta_generic_to_shared(&Bs[0][row][q * 16]);
    const unsigned STGA = 64 * 72 * 2;

    auto load_stage = [&](int s, int kt) {
        const __half* a = apb + kt * 64;
        const __half* b = bpb + kt * 64;
        unsigned da = sA0 + s * STGA, db = sB0 + s * STGA;
        if (av) {
            CPA16(da,      a);
            CPA16(da + 16, a + 8);
        } else {
            *(uint4*)&As[s][row][q * 16]     = make_uint4(0, 0, 0, 0);
            *(uint4*)&As[s][row][q * 16 + 8] = make_uint4(0, 0, 0, 0);
        }
        CPA16(db,      b);
        CPA16(db + 16, b + 8);
        asm volatile("cp.async.commit_group;\n");
    };

    float acc[4][4] = {};
    const int nk = K >> 6;
    load_stage(0, 0);
    for (int kt = 0; kt < nk; ++kt) {
        int cur = kt & 1;
        if (kt + 1 < nk) {
            load_stage(cur ^ 1, kt + 1);
            asm volatile("cp.async.wait_group 1;\n");
        } else {
            asm volatile("cp.async.wait_group 0;\n");
        }
        __syncthreads();
        #pragma unroll
        for (int ks = 0; ks < 4; ++ks) {
            int kb = ks * 16 + 2 * ti;
            unsigned a0 = *(const unsigned*)&As[cur][wr * 16 + tg    ][kb    ];
            unsigned a1 = *(const unsigned*)&As[cur][wr * 16 + tg + 8][kb    ];
            unsigned a2 = *(const unsigned*)&As[cur][wr * 16 + tg    ][kb + 8];
            unsigned a3 = *(const unsigned*)&As[cur][wr * 16 + tg + 8][kb + 8];
            #pragma unroll
            for (int nt = 0; nt < 4; ++nt) {
                int bc = wc * 32 + nt * 8 + tg;
                unsigned b0 = *(const unsigned*)&Bs[cur][bc][kb    ];
                unsigned b1 = *(const unsigned*)&Bs[cur][bc][kb + 8];
                asm volatile(
                    "mma.sync.aligned.m16n8k16.row.col.f32.f16.f16.f32 "
                    "{%0,%1,%2,%3}, {%4,%5,%6,%7}, {%8,%9}, {%0,%1,%2,%3};"
                    : "+f"(acc[nt][0]), "+f"(acc[nt][1]),
                      "+f"(acc[nt][2]), "+f"(acc[nt][3])
                    : "r"(a0), "r"(a1), "r"(a2), "r"(a3), "r"(b0), "r"(b1));
            }
        }
        __syncthreads();
    }
    #pragma unroll
    for (int nt = 0; nt < 4; ++nt) {
        int col = bn + wc * 32 + nt * 8 + 2 * ti;
        float bv0 = bias[col], bv1 = bias[col + 1];
        int r0 = bm + wr * 16 + tg, r1 = r0 + 8;
        float v00 = fmaxf(acc[nt][0] + bv0, 0.f), v01 = fmaxf(acc[nt][1] + bv1, 0.f);
        float v10 = fmaxf(acc[nt][2] + bv0, 0.f), v11 = fmaxf(acc[nt][3] + bv1, 0.f);
        if (Ch) {
            if (r0 < M) Ch[(size_t)r0 * (N / 2) + col / 2] = __floats2half2_rn(v00, v01);
            if (r1 < M) Ch[(size_t)r1 * (N / 2) + col / 2] = __floats2half2_rn(v10, v11);
        } else {
            if (r0 < M) *(float2*)(C + (size_t)r0 * N + col) = make_float2(v00, v01);
            if (r1 < M) *(float2*)(C + (size_t)r1 * N + col) = make_float2(v10, v11);
        }
    }
}

// ---------------- launch ------------------------------------------------------
extern "C" void kernel_launch(void* const* d_in, const int* in_sizes, int n_in,
                              void* d_out, int out_size) {
    const float* x      = (const float*)d_in[0];
    const int*   ei     = (const int*)  d_in[1];
    const float* pseudo = (const float*)d_in[2];
    const float* g1     = (const float*)d_in[3];
    const float* mu1    = (const float*)d_in[4];
    const float* sigma1 = (const float*)d_in[5];
    const float* root1  = (const float*)d_in[6];
    const float* b1     = (const float*)d_in[7];
    const float* g2     = (const float*)d_in[8];
    const float* mu2    = (const float*)d_in[9];
    const float* sigma2 = (const float*)d_in[10];
    const float* root2  = (const float*)d_in[11];
    const float* b2     = (const float*)d_in[12];
    const float* gs     = (const float*)d_in[13];
    const float* mus    = (const float*)d_in[14];
    const float* sigmas = (const float*)d_in[15];
    const float* roots  = (const float*)d_in[16];
    const float* bs     = (const float*)d_in[17];
    float* out = (float*)d_out;

    __half *t1p, *t2p, *B1p, *B2p;
    __half2 *hhp;
    float *bias2p;
    cudaGetSymbolAddress((void**)&t1p, d_t1h);
    cudaGetSymbolAddress((void**)&t2p, d_t2h);
    cudaGetSymbolAddress((void**)&hhp, d_hh);
    cudaGetSymbolAddress((void**)&B1p, d_B1h);
    cudaGetSymbolAddress((void**)&B2p, d_B2h);
    cudaGetSymbolAddress((void**)&bias2p, d_bias2);

    const int MT = (N_NODES + 63) / 64;
    const int EW = (N_EDGES + 255) / 256;
    const int NW = (N_NODES * 32 + 255) / 256;

    // prep
    hist_dst<<<EW, 256>>>(ei, x);
    scan_all<<<NB, 256>>>();
    scatter_idx<<<EW, 256>>>(ei);

    // x-pass (launch #4 -> ncu capture slot)
    tbuildX<<<NW, 256>>>(pseudo, mu1, sigma1, mus, sigmas);
    bweave<<<(128 * K2 + 255) / 256, 256>>>(g1, root1, g2, root2, gs, roots, b2, bs);
    gemm_h<<<dim3(1, MT), 256>>>(t1p, B1p, nullptr, hhp, N_NODES, 64, K1, b1);

    // h-pass: layer-2 GEMM back on BN=64 tiles (A/B test vs gemm_h2)
    tbuildH<<<NW, 256>>>(pseudo, mu2, sigma2);
    gemm_h<<<dim3(2, MT), 256>>>(t2p, B2p, out, nullptr, N_NODES, 128, K2, bias2p);
}